// round 1
// baseline (speedup 1.0000x reference)
#include <cuda_runtime.h>
#include <cuda_bf16.h>

// DepthwiseRREUp: x [B=8, C=256, G=4, H=64, W=64] fp32, dw [C,1,2,2] fp32.
// out [B, C, G, 128, 128]:
//   out[b,c,g,2i+di,2j+dj] = x[b,c,g,i,j] * f(c,g)[di,dj]
// where f(c,g) = rot90(dw[c], k=g) (CCW).
//
// dw[c] = [[a,b],[c,d]]:
//   g=0: [[a,b],[c,d]]
//   g=1: [[b,d],[a,c]]
//   g=2: [[d,c],[b,a]]
//   g=3: [[c,a],[d,b]]
//
// One thread per input float4 (4 consecutive W elements). Each thread writes
// 2 output rows x 2 float4 each (8 consecutive output columns), all coalesced.

#define HW_IN   (64 * 64)       // input plane elems
#define F4_PER_PLANE (HW_IN / 4)    // 1024 float4 per input plane
#define F4_PER_ROW   (64 / 4)       // 16 float4 per input row
#define OUT_PLANE_F4 (128 * 128 / 4) // 4096 float4 per output plane
#define OUT_ROW_F4   (128 / 4)       // 32 float4 per output row

__global__ __launch_bounds__(256)
void rre_up_kernel(const float4* __restrict__ x,
                   const float4* __restrict__ dw4,   // [C] float4 = (a,b,c,d)
                   float4* __restrict__ out,
                   int n4)                            // total input float4 count
{
    int idx = blockIdx.x * blockDim.x + threadIdx.x;
    if (idx >= n4) return;

    int plane = idx >> 10;          // (b*C + c)*G + g, 0..8191
    int p     = idx & 1023;         // within-plane float4 index
    int i     = p >> 4;             // input row 0..63
    int j4    = p & 15;             // input float4 col 0..15

    int cg = plane & (256 * 4 - 1); // c*4 + g
    int c  = cg >> 2;
    int g  = cg & 3;

    // dw is tiny (4 KB): read through L1/L2 cached path (broadcast-friendly)
    float4 w = __ldg(&dw4[c]);      // w.x=a, w.y=b, w.z=c, w.w=d

    float f00, f01, f10, f11;
    switch (g) {
        case 0: f00 = w.x; f01 = w.y; f10 = w.z; f11 = w.w; break;
        case 1: f00 = w.y; f01 = w.w; f10 = w.x; f11 = w.z; break;
        case 2: f00 = w.w; f01 = w.z; f10 = w.y; f11 = w.x; break;
        default:f00 = w.z; f01 = w.x; f10 = w.w; f11 = w.y; break;
    }

    // Streamed read: no reuse, don't pollute caches
    float4 v = __ldcs(&x[idx]);

    // Output base (float4 units)
    float4* o = out + (size_t)plane * OUT_PLANE_F4
                    + (size_t)(2 * i) * OUT_ROW_F4
                    + 2 * j4;

    float4 r0a = make_float4(v.x * f00, v.x * f01, v.y * f00, v.y * f01);
    float4 r0b = make_float4(v.z * f00, v.z * f01, v.w * f00, v.w * f01);
    float4 r1a = make_float4(v.x * f10, v.x * f11, v.y * f10, v.y * f11);
    float4 r1b = make_float4(v.z * f10, v.z * f11, v.w * f10, v.w * f11);

    __stcs(&o[0], r0a);
    __stcs(&o[1], r0b);
    __stcs(&o[OUT_ROW_F4 + 0], r1a);
    __stcs(&o[OUT_ROW_F4 + 1], r1b);
}

extern "C" void kernel_launch(void* const* d_in, const int* in_sizes, int n_in,
                              void* d_out, int out_size)
{
    const float4* x   = (const float4*)d_in[0];   // [8,256,4,64,64] f32
    const float4* dw4 = (const float4*)d_in[1];   // [256,1,2,2] f32 -> float4 per channel
    float4* out       = (float4*)d_out;           // [8,256,4,128,128] f32

    int n4 = in_sizes[0] / 4;                     // 8,388,608
    int block = 256;
    int grid  = (n4 + block - 1) / block;         // 32768
    rre_up_kernel<<<grid, block>>>(x, dw4, out, n4);
}

// round 3
// speedup vs baseline: 1.2215x; 1.2215x over previous
#include <cuda_runtime.h>
#include <cuda_bf16.h>

// DepthwiseRREUp: x [B=8, C=256, G=4, H=64, W=64] fp32, dw [C,1,2,2] fp32.
// out [B, C, G, 128, 128]:
//   out[b,c,g,2i+di,2j+dj] = x[b,c,g,i,j] * f(c,g)[di,dj],  f = rot90(dw[c], k=g) CCW.
//
// dw[c] = [[a,b],[c,d]]:
//   g=0: [[a,b],[c,d]]   g=1: [[b,d],[a,c]]   g=2: [[d,c],[b,a]]   g=3: [[c,a],[d,b]]
//
// One thread per input FLOAT2 (2 consecutive W elements). Each thread writes
// exactly one float4 per output row (2 rows), and consecutive lanes write
// consecutive float4 slots -> every STG.128 is fully lane-contiguous
// (4 wavefronts / warp, full 32B sectors covered; no half-dirty sectors).

#define OUT_PLANE_F4 4096            // 128*128/4
#define OUT_ROW_F4   32              // 128/4

__global__ __launch_bounds__(256)
void rre_up_kernel(const float2* __restrict__ x2,
                   const float4* __restrict__ dw4,   // [C] float4 = (a,b,c,d)
                   float4* __restrict__ out,
                   int n2)                            // total input float2 count
{
    int idx = blockIdx.x * blockDim.x + threadIdx.x;
    if (idx >= n2) return;

    int plane = idx >> 11;           // (b*C + c)*G + g, 0..8191
    int p     = idx & 2047;          // within-plane float2 index
    int i     = p >> 5;              // input row 0..63
    int j2    = p & 31;              // input float2 col 0..31  (== output float4 col)

    int cg = plane & (256 * 4 - 1);  // c*4 + g
    int c  = cg >> 2;
    int g  = cg & 3;

    // dw is 4 KB total; warp-uniform c -> single broadcast line via read-only path
    float4 w = __ldg(&dw4[c]);       // w.x=a, w.y=b, w.z=c, w.w=d

    float f00, f01, f10, f11;
    switch (g) {
        case 0: f00 = w.x; f01 = w.y; f10 = w.z; f11 = w.w; break;
        case 1: f00 = w.y; f01 = w.w; f10 = w.x; f11 = w.z; break;
        case 2: f00 = w.w; f01 = w.z; f10 = w.y; f11 = w.x; break;
        default:f00 = w.z; f01 = w.x; f10 = w.w; f11 = w.y; break;
    }

    // Streamed read: no reuse, bypass persistent caching
    float2 v = __ldcs(&x2[idx]);

    float4* o = out + (size_t)plane * OUT_PLANE_F4
                    + (size_t)(2 * i) * OUT_ROW_F4
                    + j2;

    float4 r0 = make_float4(v.x * f00, v.x * f01, v.y * f00, v.y * f01);
    float4 r1 = make_float4(v.x * f10, v.x * f11, v.y * f10, v.y * f11);

    __stcs(&o[0],          r0);   // row 2i,   cols 4*j2 .. 4*j2+3
    __stcs(&o[OUT_ROW_F4], r1);   // row 2i+1, same cols
}

extern "C" void kernel_launch(void* const* d_in, const int* in_sizes, int n_in,
                              void* d_out, int out_size)
{
    const float2* x2  = (const float2*)d_in[0];   // [8,256,4,64,64] f32
    const float4* dw4 = (const float4*)d_in[1];   // [256,1,2,2] f32 -> one float4 per channel
    float4* out       = (float4*)d_out;           // [8,256,4,128,128] f32

    int n2 = in_sizes[0] / 2;                     // 16,777,216
    int block = 256;
    int grid  = (n2 + block - 1) / block;         // 65536
    rre_up_kernel<<<grid, block>>>(x2, dw4, out, n2);
}